// round 1
// baseline (speedup 1.0000x reference)
#include <cuda_runtime.h>
#include <cuda_bf16.h>

#define NNODES 100000
#define NEDGES 1600000
#define DHID 128
#define DOUT 64

// Scratch (no allocations allowed -> __device__ globals)
__device__ float g_h[(size_t)NNODES * DHID];    // x @ W
__device__ float g_agg[(size_t)NNODES * DHID];  // scatter accumulator
__device__ float g_x[(size_t)NNODES * DHID];    // post BN+ReLU features
__device__ float g_stats[2 * DHID];             // per-col sum, sumsq
__device__ float g_s[DHID];                     // final weighted edge sum

// ---------------------------------------------------------------- zeroing
__global__ void zero_agg_kernel() {
    size_t n = (size_t)NNODES * DHID / 4;
    float4* p = (float4*)g_agg;
    for (size_t i = (size_t)blockIdx.x * blockDim.x + threadIdx.x; i < n;
         i += (size_t)gridDim.x * blockDim.x)
        p[i] = make_float4(0.f, 0.f, 0.f, 0.f);
}

__global__ void zero_misc_kernel() {
    int i = threadIdx.x;
    if (i < 2 * DHID) g_stats[i] = 0.f;
    if (i < DHID) g_s[i] = 0.f;
}

// ---------------------------------------------------------------- GEMM
// H[r, 0:128] = X[r, 0:128] @ W[128,128].  W staged fully in SMEM (64KB).
// Block: 256 threads -> 64 rows x 128 cols; thread = 4 rows x 8 cols.
__global__ void gemm128_kernel(const float* __restrict__ Xin,
                               const float* __restrict__ W, int nrows) {
    const float* X = Xin ? Xin : g_x;
    __shared__ float Wsh[DHID * DHID];
    __shared__ float Xsh[64 * 16];
    int tid = threadIdx.x;

    const float4* W4 = (const float4*)W;
    float4* Wsh4 = (float4*)Wsh;
#pragma unroll
    for (int i = 0; i < 16; i++) Wsh4[tid + 256 * i] = W4[tid + 256 * i];

    int tx = tid & 15, ty = tid >> 4;
    int row0 = blockIdx.x * 64 + ty * 4;
    float acc[4][8];
#pragma unroll
    for (int i = 0; i < 4; i++)
#pragma unroll
        for (int j = 0; j < 8; j++) acc[i][j] = 0.f;

    int lr = tid >> 2;          // 0..63 (row of X tile to stage)
    int lk = (tid & 3) * 4;     // 0..12
    int gr = blockIdx.x * 64 + lr;

    for (int k0 = 0; k0 < DHID; k0 += 16) {
        float4 xv = make_float4(0.f, 0.f, 0.f, 0.f);
        if (gr < nrows) xv = *(const float4*)(X + (size_t)gr * DHID + k0 + lk);
        __syncthreads();
        *(float4*)(&Xsh[lr * 16 + lk]) = xv;
        __syncthreads();
#pragma unroll
        for (int kk = 0; kk < 16; kk++) {
            float4 w0 = *(const float4*)(&Wsh[(k0 + kk) * DHID + tx * 8]);
            float4 w1 = *(const float4*)(&Wsh[(k0 + kk) * DHID + tx * 8 + 4]);
#pragma unroll
            for (int i = 0; i < 4; i++) {
                float xr = Xsh[(ty * 4 + i) * 16 + kk];
                acc[i][0] += xr * w0.x; acc[i][1] += xr * w0.y;
                acc[i][2] += xr * w0.z; acc[i][3] += xr * w0.w;
                acc[i][4] += xr * w1.x; acc[i][5] += xr * w1.y;
                acc[i][6] += xr * w1.z; acc[i][7] += xr * w1.w;
            }
        }
    }
#pragma unroll
    for (int i = 0; i < 4; i++) {
        int r = row0 + i;
        if (r < nrows) {
            *(float4*)(&g_h[(size_t)r * DHID + tx * 8]) =
                make_float4(acc[i][0], acc[i][1], acc[i][2], acc[i][3]);
            *(float4*)(&g_h[(size_t)r * DHID + tx * 8 + 4]) =
                make_float4(acc[i][4], acc[i][5], acc[i][6], acc[i][7]);
        }
    }
}

// ---------------------------------------------------------------- scatter
// One warp per edge: 32 lanes x float4 = 128 floats.
// agg[dst] += h[src] * w  via vectorized no-return reduction (red.v4.f32).
__global__ void scatter_kernel(const int* __restrict__ src,
                               const int* __restrict__ dst,
                               const float* __restrict__ ew) {
    int lane = threadIdx.x & 31;
    int warp = (blockIdx.x * blockDim.x + threadIdx.x) >> 5;
    int nw = (gridDim.x * blockDim.x) >> 5;
    for (int e = warp; e < NEDGES; e += nw) {
        int s = __ldg(src + e);
        int d = __ldg(dst + e);
        float w = __ldg(ew + e);
        float4 v = __ldg((const float4*)(g_h + (size_t)s * DHID) + lane);
        v.x *= w; v.y *= w; v.z *= w; v.w *= w;
        float* p = g_agg + (size_t)d * DHID + lane * 4;
        asm volatile("red.global.add.v4.f32 [%0], {%1,%2,%3,%4};"
                     :: "l"(p), "f"(v.x), "f"(v.y), "f"(v.z), "f"(v.w)
                     : "memory");
    }
}

// ---------------------------------------------------------------- BatchNorm
__global__ void bn_stats_kernel() {
    int col = threadIdx.x;  // 128 threads
    float s = 0.f, q = 0.f;
    for (int r = blockIdx.x; r < NNODES; r += gridDim.x) {
        float v = g_agg[(size_t)r * DHID + col];
        s += v;
        q += v * v;
    }
    atomicAdd(&g_stats[col], s);
    atomicAdd(&g_stats[DHID + col], q);
}

__global__ void bn_apply_kernel(const float* __restrict__ gamma,
                                const float* __restrict__ beta) {
    const float invN = 1.0f / (float)NNODES;
    size_t n = (size_t)NNODES * (DHID / 4);
    for (size_t i = (size_t)blockIdx.x * blockDim.x + threadIdx.x; i < n;
         i += (size_t)gridDim.x * blockDim.x) {
        int c4 = (int)(i & (DHID / 4 - 1));
        float4 v = ((const float4*)g_agg)[i];
        float vv[4] = {v.x, v.y, v.z, v.w};
        float o[4];
#pragma unroll
        for (int j = 0; j < 4; j++) {
            int c = c4 * 4 + j;
            float mu = g_stats[c] * invN;
            float var = g_stats[DHID + c] * invN - mu * mu;
            float sc = gamma[c] * rsqrtf(var + 1e-5f);
            float sh = beta[c] - mu * sc;
            float y = vv[j] * sc + sh;
            o[j] = y > 0.f ? y : 0.f;
        }
        ((float4*)g_x)[i] = make_float4(o[0], o[1], o[2], o[3]);
    }
}

// ---------------------------------------------------------------- final
// s[k] = sum_e w_e * x2[src_e][k]   (sum over dst of segment_sum == sum over edges)
__global__ void edge_reduce_kernel(const int* __restrict__ src,
                                   const float* __restrict__ ew) {
    int lane = threadIdx.x & 31;
    int warp = (blockIdx.x * blockDim.x + threadIdx.x) >> 5;
    int nw = (gridDim.x * blockDim.x) >> 5;
    float4 acc = make_float4(0.f, 0.f, 0.f, 0.f);
    for (int e = warp; e < NEDGES; e += nw) {
        int s = __ldg(src + e);
        float w = __ldg(ew + e);
        float4 v = __ldg((const float4*)(g_x + (size_t)s * DHID) + lane);
        acc.x += v.x * w; acc.y += v.y * w;
        acc.z += v.z * w; acc.w += v.w * w;
    }
    atomicAdd(&g_s[lane * 4 + 0], acc.x);
    atomicAdd(&g_s[lane * 4 + 1], acc.y);
    atomicAdd(&g_s[lane * 4 + 2], acc.z);
    atomicAdd(&g_s[lane * 4 + 3], acc.w);
}

// out[j] = s @ W2 + N * b2
__global__ void final_kernel(const float* __restrict__ W2,
                             const float* __restrict__ b2,
                             float* __restrict__ out) {
    int j = threadIdx.x;
    if (j < DOUT) {
        float acc = 0.f;
        for (int k = 0; k < DHID; k++) acc += g_s[k] * W2[k * DOUT + j];
        out[j] = acc + (float)NNODES * b2[j];
    }
}

// ----------------------------------------------------------------
extern "C" void kernel_launch(void* const* d_in, const int* in_sizes, int n_in,
                              void* d_out, int out_size) {
    const float* nf  = (const float*)d_in[0];
    const int*   ei  = (const int*)d_in[1];
    const float* ew  = (const float*)d_in[2];
    const float* W0  = (const float*)d_in[3];
    // b0 (d_in[4]) and b1 (d_in[6]) cancel exactly through BatchNorm (mean shift)
    const float* W1  = (const float*)d_in[5];
    const float* W2  = (const float*)d_in[7];
    const float* b2  = (const float*)d_in[8];
    const float* g0  = (const float*)d_in[9];
    const float* be0 = (const float*)d_in[10];
    const float* g1  = (const float*)d_in[11];
    const float* be1 = (const float*)d_in[12];
    const int* src = ei;            // edge_index[0]
    const int* dst = ei + NEDGES;   // edge_index[1]
    float* out = (float*)d_out;

    int gemmGrid = (NNODES + 63) / 64;

    // layer 0: conv -> BN -> ReLU
    gemm128_kernel<<<gemmGrid, 256>>>(nf, W0, NNODES);
    zero_agg_kernel<<<2048, 256>>>();
    scatter_kernel<<<2048, 256>>>(src, dst, ew);
    zero_misc_kernel<<<1, 256>>>();
    bn_stats_kernel<<<1024, 128>>>();
    bn_apply_kernel<<<2048, 256>>>(g0, be0);

    // layer 1
    gemm128_kernel<<<gemmGrid, 256>>>(nullptr, W1, NNODES);
    zero_agg_kernel<<<2048, 256>>>();
    scatter_kernel<<<2048, 256>>>(src, dst, ew);
    zero_misc_kernel<<<1, 256>>>();   // also re-zeroes g_s before edge_reduce
    bn_stats_kernel<<<1024, 128>>>();
    bn_apply_kernel<<<2048, 256>>>(g1, be1);

    // final conv collapsed: sum_axis0 of segment_sum == weighted edge reduce
    edge_reduce_kernel<<<1024, 256>>>(src, ew);
    final_kernel<<<1, 64>>>(W2, b2, out);
}

// round 4
// speedup vs baseline: 1.0348x; 1.0348x over previous
#include <cuda_runtime.h>
#include <cuda_bf16.h>

#define NNODES 100000
#define NEDGES 1600000
#define DHID 128
#define DOUT 64

// Scratch (no allocations allowed -> __device__ globals).
// NOTE: these must ONLY be referenced from device code (host-side address of a
// __device__ symbol is invalid — that was the R2 bug).
__device__ float g_h[(size_t)NNODES * DHID];    // x @ W
__device__ float g_agg[(size_t)NNODES * DHID];  // gathered aggregate
__device__ int   g_cnt[NNODES + 1];             // histogram / cursor
__device__ int   g_off[NNODES + 1];             // CSR offsets (by dst)
__device__ int2  g_pe[NEDGES];                  // permuted edges: {src, w_bits}
__device__ float g_stats[2 * DHID];             // per-col sum, sumsq
__device__ float g_bnsc[DHID];                  // BN scale
__device__ float g_bnsh[DHID];                  // BN shift
__device__ float g_s[DHID];                     // final weighted edge sum

// ---------------------------------------------------------------- init
__global__ void zero_init_kernel() {
    int i = blockIdx.x * blockDim.x + threadIdx.x;
    int stride = gridDim.x * blockDim.x;
    for (int j = i; j <= NNODES; j += stride) g_cnt[j] = 0;
    if (i < 2 * DHID) g_stats[i] = 0.f;
    if (i < DHID) g_s[i] = 0.f;
}

// ---------------------------------------------------------------- CSR build
__global__ void hist_kernel(const int* __restrict__ dst) {
    int i = blockIdx.x * blockDim.x + threadIdx.x;
    int stride = gridDim.x * blockDim.x;
    for (int e = i; e < NEDGES; e += stride) atomicAdd(&g_cnt[dst[e]], 1);
}

__global__ void scan_kernel() {
    __shared__ int sh[1024];
    int t = threadIdx.x;
    const int C = (NNODES + 1023) / 1024;  // 98
    int base = t * C;
    int lim = base + C < NNODES ? base + C : NNODES;
    int s = 0;
    for (int i = base; i < lim; i++) s += g_cnt[i];
    sh[t] = s;
    __syncthreads();
    for (int off = 1; off < 1024; off <<= 1) {
        int v = (t >= off) ? sh[t - off] : 0;
        __syncthreads();
        sh[t] += v;
        __syncthreads();
    }
    int run = sh[t] - s;  // exclusive prefix
    for (int i = base; i < lim; i++) {
        int c = g_cnt[i];
        g_off[i] = run;
        g_cnt[i] = run;  // becomes cursor for permute
        run += c;
    }
    if (t == 1023) g_off[NNODES] = sh[1023];
}

__global__ void permute_kernel(const int* __restrict__ src,
                               const int* __restrict__ dst,
                               const float* __restrict__ ew) {
    int i = blockIdx.x * blockDim.x + threadIdx.x;
    int stride = gridDim.x * blockDim.x;
    for (int e = i; e < NEDGES; e += stride) {
        int d = dst[e];
        int pos = atomicAdd(&g_cnt[d], 1);
        g_pe[pos] = make_int2(src[e], __float_as_int(ew[e]));
    }
}

// ---------------------------------------------------------------- GEMM
// H[r, :] = BNrelu(X[r, :]) @ W[128,128].  W staged fully in SMEM.
// 256 threads -> 64 rows x 128 cols; thread computes 4 rows x 8 cols.
// If useBN, X values are transformed relu(x*sc[c]+sh[c]) at load.
// Xin == nullptr means read from g_agg (layer-1 path).
__global__ void gemm128_kernel(const float* __restrict__ Xin,
                               const float* __restrict__ W, int useBN) {
    const float* X = Xin ? Xin : g_agg;  // evaluated in device code: valid
    __shared__ float Wsh[DHID * DHID];
    __shared__ float Xsh[64 * 16];
    int tid = threadIdx.x;

    const float4* W4 = (const float4*)W;
    float4* Wsh4 = (float4*)Wsh;
#pragma unroll
    for (int i = 0; i < 16; i++) Wsh4[tid + 256 * i] = W4[tid + 256 * i];

    int tx = tid & 15, ty = tid >> 4;
    int row0 = blockIdx.x * 64 + ty * 4;
    float acc[4][8];
#pragma unroll
    for (int i = 0; i < 4; i++)
#pragma unroll
        for (int j = 0; j < 8; j++) acc[i][j] = 0.f;

    int lr = tid >> 2;       // 0..63  row of X tile staged by this thread
    int lk = (tid & 3) * 4;  // 0,4,8,12
    int gr = blockIdx.x * 64 + lr;

    for (int k0 = 0; k0 < DHID; k0 += 16) {
        float4 xv = make_float4(0.f, 0.f, 0.f, 0.f);
        if (gr < NNODES) {
            xv = *(const float4*)(X + (size_t)gr * DHID + k0 + lk);
            if (useBN) {
                float4 sc = *(const float4*)(g_bnsc + k0 + lk);
                float4 sh = *(const float4*)(g_bnsh + k0 + lk);
                xv.x = fmaxf(0.f, xv.x * sc.x + sh.x);
                xv.y = fmaxf(0.f, xv.y * sc.y + sh.y);
                xv.z = fmaxf(0.f, xv.z * sc.z + sh.z);
                xv.w = fmaxf(0.f, xv.w * sc.w + sh.w);
            }
        }
        __syncthreads();
        *(float4*)(&Xsh[lr * 16 + lk]) = xv;
        __syncthreads();
#pragma unroll
        for (int kk = 0; kk < 16; kk++) {
            float4 w0 = *(const float4*)(&Wsh[(k0 + kk) * DHID + tx * 8]);
            float4 w1 = *(const float4*)(&Wsh[(k0 + kk) * DHID + tx * 8 + 4]);
#pragma unroll
            for (int i = 0; i < 4; i++) {
                float xr = Xsh[(ty * 4 + i) * 16 + kk];
                acc[i][0] += xr * w0.x; acc[i][1] += xr * w0.y;
                acc[i][2] += xr * w0.z; acc[i][3] += xr * w0.w;
                acc[i][4] += xr * w1.x; acc[i][5] += xr * w1.y;
                acc[i][6] += xr * w1.z; acc[i][7] += xr * w1.w;
            }
        }
    }
#pragma unroll
    for (int i = 0; i < 4; i++) {
        int r = row0 + i;
        if (r < NNODES) {
            *(float4*)(&g_h[(size_t)r * DHID + tx * 8]) =
                make_float4(acc[i][0], acc[i][1], acc[i][2], acc[i][3]);
            *(float4*)(&g_h[(size_t)r * DHID + tx * 8 + 4]) =
                make_float4(acc[i][4], acc[i][5], acc[i][6], acc[i][7]);
        }
    }
}

// ---------------------------------------------------------------- gather conv
// One warp per node: agg[n] = sum_{e in CSR row n} w_e * h[src_e].
// Reads g_h directly (device-side reference). Fused BN statistics:
// per-lane register accumulation -> smem -> global atomics.
__global__ void gather_conv_kernel() {
    int lane = threadIdx.x & 31;
    int warp = (blockIdx.x * blockDim.x + threadIdx.x) >> 5;
    int nw = (gridDim.x * blockDim.x) >> 5;
    float4 s4 = make_float4(0.f, 0.f, 0.f, 0.f);
    float4 q4 = make_float4(0.f, 0.f, 0.f, 0.f);

    for (int n = warp; n < NNODES; n += nw) {
        int beg = __ldg(&g_off[n]);
        int end = __ldg(&g_off[n + 1]);
        float4 acc = make_float4(0.f, 0.f, 0.f, 0.f);
        for (int e = beg; e < end; e++) {
            int2 pe = __ldg(&g_pe[e]);
            float w = __int_as_float(pe.y);
            float4 v = __ldg((const float4*)(g_h + (size_t)pe.x * DHID) + lane);
            acc.x += v.x * w; acc.y += v.y * w;
            acc.z += v.z * w; acc.w += v.w * w;
        }
        ((float4*)(g_agg + (size_t)n * DHID))[lane] = acc;
        s4.x += acc.x; s4.y += acc.y; s4.z += acc.z; s4.w += acc.w;
        q4.x += acc.x * acc.x; q4.y += acc.y * acc.y;
        q4.z += acc.z * acc.z; q4.w += acc.w * acc.w;
    }

    __shared__ float st[2 * DHID];
    if (threadIdx.x < 2 * DHID) st[threadIdx.x] = 0.f;
    __syncthreads();
    int c = lane * 4;
    atomicAdd(&st[c + 0], s4.x); atomicAdd(&st[c + 1], s4.y);
    atomicAdd(&st[c + 2], s4.z); atomicAdd(&st[c + 3], s4.w);
    atomicAdd(&st[DHID + c + 0], q4.x); atomicAdd(&st[DHID + c + 1], q4.y);
    atomicAdd(&st[DHID + c + 2], q4.z); atomicAdd(&st[DHID + c + 3], q4.w);
    __syncthreads();
    if (threadIdx.x < 2 * DHID) atomicAdd(&g_stats[threadIdx.x], st[threadIdx.x]);
}

// ---------------------------------------------------------------- BN finalize
// stats -> (scale, shift), then reset stats for the next layer.
__global__ void bn_finalize_kernel(const float* __restrict__ gamma,
                                   const float* __restrict__ beta) {
    int c = threadIdx.x;  // 128 threads
    const float invN = 1.0f / (float)NNODES;
    float mu = g_stats[c] * invN;
    float var = g_stats[DHID + c] * invN - mu * mu;
    float sc = gamma[c] * rsqrtf(var + 1e-5f);
    g_bnsc[c] = sc;
    g_bnsh[c] = beta[c] - mu * sc;
    g_stats[c] = 0.f;
    g_stats[DHID + c] = 0.f;
}

// ---------------------------------------------------------------- final
// s[k] = sum_e w_e * relu(bn1(agg1))[src_e][k]
__global__ void edge_reduce_kernel(const int* __restrict__ src,
                                   const float* __restrict__ ew) {
    int lane = threadIdx.x & 31;
    int warp = (blockIdx.x * blockDim.x + threadIdx.x) >> 5;
    int nw = (gridDim.x * blockDim.x) >> 5;
    float4 sc = ((const float4*)g_bnsc)[lane];
    float4 sh = ((const float4*)g_bnsh)[lane];
    float4 acc = make_float4(0.f, 0.f, 0.f, 0.f);
    for (int e = warp; e < NEDGES; e += nw) {
        int s = __ldg(src + e);
        float w = __ldg(ew + e);
        float4 v = __ldg((const float4*)(g_agg + (size_t)s * DHID) + lane);
        v.x = fmaxf(0.f, v.x * sc.x + sh.x);
        v.y = fmaxf(0.f, v.y * sc.y + sh.y);
        v.z = fmaxf(0.f, v.z * sc.z + sh.z);
        v.w = fmaxf(0.f, v.w * sc.w + sh.w);
        acc.x += v.x * w; acc.y += v.y * w;
        acc.z += v.z * w; acc.w += v.w * w;
    }
    atomicAdd(&g_s[lane * 4 + 0], acc.x);
    atomicAdd(&g_s[lane * 4 + 1], acc.y);
    atomicAdd(&g_s[lane * 4 + 2], acc.z);
    atomicAdd(&g_s[lane * 4 + 3], acc.w);
}

// out[j] = s @ W2 + N * b2
__global__ void final_kernel(const float* __restrict__ W2,
                             const float* __restrict__ b2,
                             float* __restrict__ out) {
    int j = threadIdx.x;
    if (j < DOUT) {
        float acc = 0.f;
        for (int k = 0; k < DHID; k++) acc += g_s[k] * W2[k * DOUT + j];
        out[j] = acc + (float)NNODES * b2[j];
    }
}

// ----------------------------------------------------------------
extern "C" void kernel_launch(void* const* d_in, const int* in_sizes, int n_in,
                              void* d_out, int out_size) {
    const float* nf  = (const float*)d_in[0];
    const int*   ei  = (const int*)d_in[1];
    const float* ew  = (const float*)d_in[2];
    const float* W0  = (const float*)d_in[3];
    // b0 (d_in[4]) and b1 (d_in[6]) cancel exactly through BatchNorm
    const float* W1  = (const float*)d_in[5];
    const float* W2  = (const float*)d_in[7];
    const float* b2  = (const float*)d_in[8];
    const float* g0  = (const float*)d_in[9];
    const float* be0 = (const float*)d_in[10];
    const float* g1  = (const float*)d_in[11];
    const float* be1 = (const float*)d_in[12];
    const int* src = ei;           // edge_index[0]
    const int* dst = ei + NEDGES;  // edge_index[1]
    float* out = (float*)d_out;

    int gemmGrid = (NNODES + 63) / 64;

    // CSR build (by dst), reused by both conv layers
    zero_init_kernel<<<512, 256>>>();
    hist_kernel<<<1024, 256>>>(dst);
    scan_kernel<<<1, 1024>>>();
    permute_kernel<<<1024, 256>>>(src, dst, ew);

    // layer 0: gemm -> gather(+stats) ; BN applied lazily by next consumer
    gemm128_kernel<<<gemmGrid, 256>>>(nf, W0, 0);
    gather_conv_kernel<<<1024, 256>>>();
    bn_finalize_kernel<<<1, 128>>>(g0, be0);

    // layer 1: gemm (BN0+ReLU on load) -> gather(+stats)
    gemm128_kernel<<<gemmGrid, 256>>>(nullptr, W1, 1);
    gather_conv_kernel<<<1024, 256>>>();
    bn_finalize_kernel<<<1, 128>>>(g1, be1);

    // final conv collapsed: out = (sum_e w_e * relu(bn1(agg))[src_e]) @ W2 + N*b2
    edge_reduce_kernel<<<1024, 256>>>(src, ew);
    final_kernel<<<1, 64>>>(W2, b2, out);
}

// round 6
// speedup vs baseline: 1.7412x; 1.6827x over previous
#include <cuda_runtime.h>
#include <cuda_bf16.h>
#include <cstdint>

#define NNODES 100000
#define NEDGES 1600000
#define DHID 128
#define DOUT 64
#define NTILES ((NNODES + 127) / 128)   // 782

// ---------------- device scratch (referenced ONLY from device code) ----------
__device__ __nv_bfloat16 g_h[(size_t)NNODES * DHID];   // GEMM output, bf16
__device__ float g_agg[(size_t)NNODES * DHID];         // gathered aggregate
__device__ int   g_cnt[NNODES + 1];                    // histogram / cursor
__device__ int   g_off[NNODES + 1];                    // CSR offsets (by dst)
__device__ int2  g_pe[NEDGES];                         // permuted edges {src, w}
__device__ float g_wout[NNODES];                       // per-node outgoing weight
__device__ float g_stats[2 * DHID];
__device__ float g_bnsc[DHID];
__device__ float g_bnsh[DHID];
__device__ float g_s[DHID];

// ---------------- init -------------------------------------------------------
__global__ void zero_init_kernel() {
    int i = blockIdx.x * blockDim.x + threadIdx.x;
    int stride = gridDim.x * blockDim.x;
    for (int j = i; j <= NNODES; j += stride) g_cnt[j] = 0;
    for (int j = i; j < NNODES; j += stride) g_wout[j] = 0.f;
    if (i < 2 * DHID) g_stats[i] = 0.f;
    if (i < DHID) g_s[i] = 0.f;
}

// ---------------- CSR build + out-weight histogram ---------------------------
__global__ void hist_kernel(const int* __restrict__ src,
                            const int* __restrict__ dst,
                            const float* __restrict__ ew) {
    int i = blockIdx.x * blockDim.x + threadIdx.x;
    int stride = gridDim.x * blockDim.x;
    for (int e = i; e < NEDGES; e += stride) {
        atomicAdd(&g_cnt[dst[e]], 1);
        atomicAdd(&g_wout[src[e]], ew[e]);
    }
}

__global__ void scan_kernel() {
    __shared__ int sh[1024];
    int t = threadIdx.x;
    const int C = (NNODES + 1023) / 1024;
    int base = t * C;
    int lim = base + C < NNODES ? base + C : NNODES;
    int s = 0;
    for (int i = base; i < lim; i++) s += g_cnt[i];
    sh[t] = s;
    __syncthreads();
    for (int off = 1; off < 1024; off <<= 1) {
        int v = (t >= off) ? sh[t - off] : 0;
        __syncthreads();
        sh[t] += v;
        __syncthreads();
    }
    int run = sh[t] - s;
    for (int i = base; i < lim; i++) {
        int c = g_cnt[i];
        g_off[i] = run;
        g_cnt[i] = run;
        run += c;
    }
    if (t == 1023) g_off[NNODES] = sh[1023];
}

__global__ void permute_kernel(const int* __restrict__ src,
                               const int* __restrict__ dst,
                               const float* __restrict__ ew) {
    int i = blockIdx.x * blockDim.x + threadIdx.x;
    int stride = gridDim.x * blockDim.x;
    for (int e = i; e < NEDGES; e += stride) {
        int d = dst[e];
        int pos = atomicAdd(&g_cnt[d], 1);
        g_pe[pos] = make_int2(src[e], __float_as_int(ew[e]));
    }
}

// ---------------- HMMA bf16 GEMM: H = bnrelu?(X) @ W  ------------------------
// mma.sync.m16n8k16 bf16, fp32 accum. Per CTA: 128 rows x 128 cols.
// 8 warps: warp_m = wid&3 (32 rows), warp_n = wid>>2 (64 cols).
// A_sh / Bt_sh padded to stride 136 halves (272B) -> conflict-free frag loads.
#define ST 136

__device__ __forceinline__ void mma16816(float* c, uint32_t a0, uint32_t a1,
                                         uint32_t a2, uint32_t a3,
                                         uint32_t b0, uint32_t b1) {
    asm volatile(
        "mma.sync.aligned.m16n8k16.row.col.f32.bf16.bf16.f32 "
        "{%0,%1,%2,%3}, {%4,%5,%6,%7}, {%8,%9}, {%0,%1,%2,%3};"
        : "+f"(c[0]), "+f"(c[1]), "+f"(c[2]), "+f"(c[3])
        : "r"(a0), "r"(a1), "r"(a2), "r"(a3), "r"(b0), "r"(b1));
}

__global__ void __launch_bounds__(256)
gemm_hmma_kernel(const float* __restrict__ Xin, const float* __restrict__ W,
                 int useBN) {
    extern __shared__ __nv_bfloat16 sm[];
    __nv_bfloat16* A_sh = sm;              // [128][ST]
    __nv_bfloat16* B_sh = sm + 128 * ST;   // Bt: [n][k], [128][ST]
    const int tid = threadIdx.x;
    const int row0 = blockIdx.x * 128;
    const float* X = Xin ? Xin : g_agg;

    // stage A: fp32 -> [BN+ReLU] -> bf16
    for (int i = tid; i < 8192; i += 256) {
        int r = i >> 6;
        int c = (i & 63) * 2;
        float2 xv = make_float2(0.f, 0.f);
        int gr = row0 + r;
        if (gr < NNODES) {
            xv = *(const float2*)(X + (size_t)gr * DHID + c);
            if (useBN) {
                float2 sc = *(const float2*)(g_bnsc + c);
                float2 sh = *(const float2*)(g_bnsh + c);
                xv.x = fmaxf(0.f, xv.x * sc.x + sh.x);
                xv.y = fmaxf(0.f, xv.y * sc.y + sh.y);
            }
        }
        __nv_bfloat162 bv = __floats2bfloat162_rn(xv.x, xv.y);
        *(uint32_t*)(A_sh + r * ST + c) = *(uint32_t*)&bv;
    }
    // stage Bt[n][k] = bf16(W[k][n])  (coalesced gmem read, scattered smem write)
    for (int i = tid; i < 8192; i += 256) {
        int k = i >> 6;
        int n = (i & 63) * 2;
        float2 wv = *(const float2*)(W + (size_t)k * DHID + n);
        B_sh[(n + 0) * ST + k] = __float2bfloat16(wv.x);
        B_sh[(n + 1) * ST + k] = __float2bfloat16(wv.y);
    }
    __syncthreads();

    const int wid = tid >> 5, lane = tid & 31;
    const int wm = (wid & 3) * 32;       // warp row base in tile
    const int wn = (wid >> 2) * 64;      // warp col base
    const int g = lane >> 2, q = lane & 3;

    float acc[2][8][4];
#pragma unroll
    for (int mt = 0; mt < 2; mt++)
#pragma unroll
        for (int nt = 0; nt < 8; nt++)
#pragma unroll
            for (int j = 0; j < 4; j++) acc[mt][nt][j] = 0.f;

#pragma unroll
    for (int ks = 0; ks < 8; ks++) {
        int k0 = ks * 16;
        uint32_t af[2][4];
#pragma unroll
        for (int mt = 0; mt < 2; mt++) {
            const __nv_bfloat16* ap = A_sh + (wm + mt * 16 + g) * ST + k0 + q * 2;
            af[mt][0] = *(const uint32_t*)(ap);
            af[mt][1] = *(const uint32_t*)(ap + 8 * ST);
            af[mt][2] = *(const uint32_t*)(ap + 8);
            af[mt][3] = *(const uint32_t*)(ap + 8 * ST + 8);
        }
#pragma unroll
        for (int nt = 0; nt < 8; nt++) {
            const __nv_bfloat16* bp = B_sh + (wn + nt * 8 + g) * ST + k0 + q * 2;
            uint32_t b0 = *(const uint32_t*)(bp);
            uint32_t b1 = *(const uint32_t*)(bp + 8);
#pragma unroll
            for (int mt = 0; mt < 2; mt++)
                mma16816(acc[mt][nt], af[mt][0], af[mt][1], af[mt][2], af[mt][3],
                         b0, b1);
        }
    }

    // epilogue: fp32 -> bf16 stores into g_h
#pragma unroll
    for (int mt = 0; mt < 2; mt++) {
        int r0 = row0 + wm + mt * 16 + g;
        int r1 = r0 + 8;
#pragma unroll
        for (int nt = 0; nt < 8; nt++) {
            int col = wn + nt * 8 + q * 2;
            if (r0 < NNODES) {
                __nv_bfloat162 v = __floats2bfloat162_rn(acc[mt][nt][0],
                                                         acc[mt][nt][1]);
                *(uint32_t*)(g_h + (size_t)r0 * DHID + col) = *(uint32_t*)&v;
            }
            if (r1 < NNODES) {
                __nv_bfloat162 v = __floats2bfloat162_rn(acc[mt][nt][2],
                                                         acc[mt][nt][3]);
                *(uint32_t*)(g_h + (size_t)r1 * DHID + col) = *(uint32_t*)&v;
            }
        }
    }
}

// ---------------- gather conv (bf16 reads) + fused BN stats ------------------
__global__ void gather_conv_kernel() {
    int lane = threadIdx.x & 31;
    int warp = (blockIdx.x * blockDim.x + threadIdx.x) >> 5;
    int nw = (gridDim.x * blockDim.x) >> 5;
    float4 s4 = make_float4(0.f, 0.f, 0.f, 0.f);
    float4 q4 = make_float4(0.f, 0.f, 0.f, 0.f);

    for (int n = warp; n < NNODES; n += nw) {
        int beg = __ldg(&g_off[n]);
        int end = __ldg(&g_off[n + 1]);
        float4 acc = make_float4(0.f, 0.f, 0.f, 0.f);
        for (int e = beg; e < end; e++) {
            int2 pe = __ldg(&g_pe[e]);
            float w = __int_as_float(pe.y);
            uint2 hv = __ldg((const uint2*)(g_h + (size_t)pe.x * DHID) + lane);
            float2 f0 = __bfloat1622float2(*(__nv_bfloat162*)&hv.x);
            float2 f1 = __bfloat1622float2(*(__nv_bfloat162*)&hv.y);
            acc.x += f0.x * w; acc.y += f0.y * w;
            acc.z += f1.x * w; acc.w += f1.y * w;
        }
        ((float4*)(g_agg + (size_t)n * DHID))[lane] = acc;
        s4.x += acc.x; s4.y += acc.y; s4.z += acc.z; s4.w += acc.w;
        q4.x += acc.x * acc.x; q4.y += acc.y * acc.y;
        q4.z += acc.z * acc.z; q4.w += acc.w * acc.w;
    }

    __shared__ float st[2 * DHID];
    if (threadIdx.x < 2 * DHID) st[threadIdx.x] = 0.f;
    __syncthreads();
    int c = lane * 4;
    atomicAdd(&st[c + 0], s4.x); atomicAdd(&st[c + 1], s4.y);
    atomicAdd(&st[c + 2], s4.z); atomicAdd(&st[c + 3], s4.w);
    atomicAdd(&st[DHID + c + 0], q4.x); atomicAdd(&st[DHID + c + 1], q4.y);
    atomicAdd(&st[DHID + c + 2], q4.z); atomicAdd(&st[DHID + c + 3], q4.w);
    __syncthreads();
    if (threadIdx.x < 2 * DHID) atomicAdd(&g_stats[threadIdx.x], st[threadIdx.x]);
}

// ---------------- BN finalize ------------------------------------------------
__global__ void bn_finalize_kernel(const float* __restrict__ gamma,
                                   const float* __restrict__ beta) {
    int c = threadIdx.x;
    const float invN = 1.0f / (float)NNODES;
    float mu = g_stats[c] * invN;
    float var = g_stats[DHID + c] * invN - mu * mu;
    float sc = gamma[c] * rsqrtf(var + 1e-5f);
    g_bnsc[c] = sc;
    g_bnsh[c] = beta[c] - mu * sc;
    g_stats[c] = 0.f;
    g_stats[DHID + c] = 0.f;
}

// ---------------- final: s = sum_n w_out[n] * relu(bn(agg[n])) ---------------
__global__ void node_reduce_kernel() {
    int c = threadIdx.x;   // 128 threads
    float sc = g_bnsc[c], sh = g_bnsh[c];
    float s = 0.f;
    for (int n = blockIdx.x; n < NNODES; n += gridDim.x) {
        float v = g_agg[(size_t)n * DHID + c];
        v = fmaxf(0.f, v * sc + sh);
        s += v * g_wout[n];
    }
    atomicAdd(&g_s[c], s);
}

// out[j] = s @ W2 + N * b2
__global__ void final_kernel(const float* __restrict__ W2,
                             const float* __restrict__ b2,
                             float* __restrict__ out) {
    int j = threadIdx.x;
    if (j < DOUT) {
        float acc = 0.f;
        for (int k = 0; k < DHID; k++) acc += g_s[k] * W2[k * DOUT + j];
        out[j] = acc + (float)NNODES * b2[j];
    }
}

// ----------------------------------------------------------------------------
#define GEMM_SMEM (2 * 128 * ST * 2)   // 69632 bytes

extern "C" void kernel_launch(void* const* d_in, const int* in_sizes, int n_in,
                              void* d_out, int out_size) {
    const float* nf  = (const float*)d_in[0];
    const int*   ei  = (const int*)d_in[1];
    const float* ew  = (const float*)d_in[2];
    const float* W0  = (const float*)d_in[3];
    // b0 (d_in[4]) and b1 (d_in[6]) cancel exactly through BatchNorm
    const float* W1  = (const float*)d_in[5];
    const float* W2  = (const float*)d_in[7];
    const float* b2  = (const float*)d_in[8];
    const float* g0  = (const float*)d_in[9];
    const float* be0 = (const float*)d_in[10];
    const float* g1  = (const float*)d_in[11];
    const float* be1 = (const float*)d_in[12];
    const int* src = ei;
    const int* dst = ei + NEDGES;
    float* out = (float*)d_out;

    static int smem_set = 0;
    if (!smem_set) {
        cudaFuncSetAttribute(gemm_hmma_kernel,
                             cudaFuncAttributeMaxDynamicSharedMemorySize,
                             GEMM_SMEM);
        smem_set = 1;
    }

    // CSR build (by dst) + w_out histogram, reused by both conv layers
    zero_init_kernel<<<512, 256>>>();
    hist_kernel<<<1024, 256>>>(src, dst, ew);
    scan_kernel<<<1, 1024>>>();
    permute_kernel<<<1024, 256>>>(src, dst, ew);

    // layer 0
    gemm_hmma_kernel<<<NTILES, 256, GEMM_SMEM>>>(nf, W0, 0);
    gather_conv_kernel<<<1024, 256>>>();
    bn_finalize_kernel<<<1, 128>>>(g0, be0);

    // layer 1 (BN0+ReLU fused into A-staging)
    gemm_hmma_kernel<<<NTILES, 256, GEMM_SMEM>>>(nullptr, W1, 1);
    gather_conv_kernel<<<1024, 256>>>();
    bn_finalize_kernel<<<1, 128>>>(g1, be1);

    // final conv collapsed twice: edge sum == w_out-weighted node sum
    node_reduce_kernel<<<2048, 128>>>();
    final_kernel<<<1, 64>>>(W2, b2, out);
}

// round 8
// speedup vs baseline: 1.8471x; 1.0608x over previous
#include <cuda_runtime.h>
#include <cuda_bf16.h>
#include <cstdint>

#define NNODES 100000
#define NEDGES 1600000
#define DHID 128
#define DOUT 64
#define NTILES ((NNODES + 127) / 128)   // 782

// ---------------- device scratch (referenced ONLY from device code) ----------
__device__ __nv_bfloat16 g_h[(size_t)NNODES * DHID];   // GEMM output, bf16
__device__ float g_agg[(size_t)NNODES * DHID];         // gathered aggregate
__device__ int   g_cnt[NNODES + 1];                    // histogram / cursor
__device__ int   g_off[NNODES + 1];                    // CSR offsets (by dst)
__device__ int2  g_pe[NEDGES + 4];                     // permuted edges {src, w} (+pad)
__device__ float g_wout[NNODES];                       // per-node outgoing weight
__device__ float g_stats[2 * DHID];
__device__ float g_bnsc[DHID];
__device__ float g_bnsh[DHID];
__device__ float g_s[DHID];

// ---------------- init -------------------------------------------------------
__global__ void zero_init_kernel() {
    int i = blockIdx.x * blockDim.x + threadIdx.x;
    int stride = gridDim.x * blockDim.x;
    for (int j = i; j <= NNODES; j += stride) g_cnt[j] = 0;
    for (int j = i; j < NNODES; j += stride) g_wout[j] = 0.f;
    if (i < 2 * DHID) g_stats[i] = 0.f;
    if (i < DHID) g_s[i] = 0.f;
}

// ---------------- CSR build + out-weight histogram ---------------------------
__global__ void hist_kernel(const int* __restrict__ src,
                            const int* __restrict__ dst,
                            const float* __restrict__ ew) {
    int i = blockIdx.x * blockDim.x + threadIdx.x;
    int stride = gridDim.x * blockDim.x;
    for (int e = i; e < NEDGES; e += stride) {
        atomicAdd(&g_cnt[dst[e]], 1);
        atomicAdd(&g_wout[src[e]], ew[e]);
    }
}

__global__ void scan_kernel() {
    __shared__ int sh[1024];
    int t = threadIdx.x;
    const int C = (NNODES + 1023) / 1024;
    int base = t * C;
    int lim = base + C < NNODES ? base + C : NNODES;
    int s = 0;
    for (int i = base; i < lim; i++) s += g_cnt[i];
    sh[t] = s;
    __syncthreads();
    for (int off = 1; off < 1024; off <<= 1) {
        int v = (t >= off) ? sh[t - off] : 0;
        __syncthreads();
        sh[t] += v;
        __syncthreads();
    }
    int run = sh[t] - s;
    for (int i = base; i < lim; i++) {
        int c = g_cnt[i];
        g_off[i] = run;
        g_cnt[i] = run;
        run += c;
    }
    if (t == 1023) g_off[NNODES] = sh[1023];
}

__global__ void permute_kernel(const int* __restrict__ src,
                               const int* __restrict__ dst,
                               const float* __restrict__ ew) {
    int i = blockIdx.x * blockDim.x + threadIdx.x;
    int stride = gridDim.x * blockDim.x;
    for (int e = i; e < NEDGES; e += stride) {
        int d = dst[e];
        int pos = atomicAdd(&g_cnt[d], 1);
        g_pe[pos] = make_int2(src[e], __float_as_int(ew[e]));
    }
}

// ---------------- HMMA bf16 GEMM: H = bnrelu?(X) @ W  ------------------------
#define ST 136

__device__ __forceinline__ void mma16816(float* c, uint32_t a0, uint32_t a1,
                                         uint32_t a2, uint32_t a3,
                                         uint32_t b0, uint32_t b1) {
    asm volatile(
        "mma.sync.aligned.m16n8k16.row.col.f32.bf16.bf16.f32 "
        "{%0,%1,%2,%3}, {%4,%5,%6,%7}, {%8,%9}, {%0,%1,%2,%3};"
        : "+f"(c[0]), "+f"(c[1]), "+f"(c[2]), "+f"(c[3])
        : "r"(a0), "r"(a1), "r"(a2), "r"(a3), "r"(b0), "r"(b1));
}

__global__ void __launch_bounds__(256)
gemm_hmma_kernel(const float* __restrict__ Xin, const float* __restrict__ W,
                 int useBN) {
    extern __shared__ __nv_bfloat16 sm[];
    __nv_bfloat16* A_sh = sm;              // [128][ST]
    __nv_bfloat16* B_sh = sm + 128 * ST;   // Bt: [n][k], [128][ST]
    const int tid = threadIdx.x;
    const int row0 = blockIdx.x * 128;
    const float* X = Xin ? Xin : g_agg;

    for (int i = tid; i < 8192; i += 256) {
        int r = i >> 6;
        int c = (i & 63) * 2;
        float2 xv = make_float2(0.f, 0.f);
        int gr = row0 + r;
        if (gr < NNODES) {
            xv = *(const float2*)(X + (size_t)gr * DHID + c);
            if (useBN) {
                float2 sc = *(const float2*)(g_bnsc + c);
                float2 sh = *(const float2*)(g_bnsh + c);
                xv.x = fmaxf(0.f, xv.x * sc.x + sh.x);
                xv.y = fmaxf(0.f, xv.y * sc.y + sh.y);
            }
        }
        __nv_bfloat162 bv = __floats2bfloat162_rn(xv.x, xv.y);
        *(uint32_t*)(A_sh + r * ST + c) = *(uint32_t*)&bv;
    }
    for (int i = tid; i < 8192; i += 256) {
        int k = i >> 6;
        int n = (i & 63) * 2;
        float2 wv = *(const float2*)(W + (size_t)k * DHID + n);
        B_sh[(n + 0) * ST + k] = __float2bfloat16(wv.x);
        B_sh[(n + 1) * ST + k] = __float2bfloat16(wv.y);
    }
    __syncthreads();

    const int wid = tid >> 5, lane = tid & 31;
    const int wm = (wid & 3) * 32;
    const int wn = (wid >> 2) * 64;
    const int g = lane >> 2, q = lane & 3;

    float acc[2][8][4];
#pragma unroll
    for (int mt = 0; mt < 2; mt++)
#pragma unroll
        for (int nt = 0; nt < 8; nt++)
#pragma unroll
            for (int j = 0; j < 4; j++) acc[mt][nt][j] = 0.f;

#pragma unroll
    for (int ks = 0; ks < 8; ks++) {
        int k0 = ks * 16;
        uint32_t af[2][4];
#pragma unroll
        for (int mt = 0; mt < 2; mt++) {
            const __nv_bfloat16* ap = A_sh + (wm + mt * 16 + g) * ST + k0 + q * 2;
            af[mt][0] = *(const uint32_t*)(ap);
            af[mt][1] = *(const uint32_t*)(ap + 8 * ST);
            af[mt][2] = *(const uint32_t*)(ap + 8);
            af[mt][3] = *(const uint32_t*)(ap + 8 * ST + 8);
        }
#pragma unroll
        for (int nt = 0; nt < 8; nt++) {
            const __nv_bfloat16* bp = B_sh + (wn + nt * 8 + g) * ST + k0 + q * 2;
            uint32_t b0 = *(const uint32_t*)(bp);
            uint32_t b1 = *(const uint32_t*)(bp + 8);
#pragma unroll
            for (int mt = 0; mt < 2; mt++)
                mma16816(acc[mt][nt], af[mt][0], af[mt][1], af[mt][2], af[mt][3],
                         b0, b1);
        }
    }

#pragma unroll
    for (int mt = 0; mt < 2; mt++) {
        int r0 = row0 + wm + mt * 16 + g;
        int r1 = r0 + 8;
#pragma unroll
        for (int nt = 0; nt < 8; nt++) {
            int col = wn + nt * 8 + q * 2;
            if (r0 < NNODES) {
                __nv_bfloat162 v = __floats2bfloat162_rn(acc[mt][nt][0],
                                                         acc[mt][nt][1]);
                *(uint32_t*)(g_h + (size_t)r0 * DHID + col) = *(uint32_t*)&v;
            }
            if (r1 < NNODES) {
                __nv_bfloat162 v = __floats2bfloat162_rn(acc[mt][nt][2],
                                                         acc[mt][nt][3]);
                *(uint32_t*)(g_h + (size_t)r1 * DHID + col) = *(uint32_t*)&v;
            }
        }
    }
}

// ---------------- gather conv (bf16 reads, MLP-4 inner loop) -----------------
// One warp per node. 4 edges per iteration via 4 independent int2 loads
// (8B-aligned always), then 4 INDEPENDENT row loads before any FMA.
__global__ void gather_conv_kernel() {
    int lane = threadIdx.x & 31;
    int warp = (blockIdx.x * blockDim.x + threadIdx.x) >> 5;
    int nw = (gridDim.x * blockDim.x) >> 5;
    float4 s4 = make_float4(0.f, 0.f, 0.f, 0.f);
    float4 q4 = make_float4(0.f, 0.f, 0.f, 0.f);

    for (int n = warp; n < NNODES; n += nw) {
        int beg = __ldg(&g_off[n]);
        int end = __ldg(&g_off[n + 1]);
        float4 acc = make_float4(0.f, 0.f, 0.f, 0.f);
        int e = beg;
        for (; e + 4 <= end; e += 4) {
            int2 p0 = __ldg(g_pe + e);
            int2 p1 = __ldg(g_pe + e + 1);
            int2 p2 = __ldg(g_pe + e + 2);
            int2 p3 = __ldg(g_pe + e + 3);
            uint2 h0 = __ldg((const uint2*)(g_h + (size_t)p0.x * DHID) + lane);
            uint2 h1 = __ldg((const uint2*)(g_h + (size_t)p1.x * DHID) + lane);
            uint2 h2 = __ldg((const uint2*)(g_h + (size_t)p2.x * DHID) + lane);
            uint2 h3 = __ldg((const uint2*)(g_h + (size_t)p3.x * DHID) + lane);
            float w0 = __int_as_float(p0.y), w1 = __int_as_float(p1.y);
            float w2 = __int_as_float(p2.y), w3 = __int_as_float(p3.y);
            float2 a0 = __bfloat1622float2(*(__nv_bfloat162*)&h0.x);
            float2 b0 = __bfloat1622float2(*(__nv_bfloat162*)&h0.y);
            float2 a1 = __bfloat1622float2(*(__nv_bfloat162*)&h1.x);
            float2 b1 = __bfloat1622float2(*(__nv_bfloat162*)&h1.y);
            float2 a2 = __bfloat1622float2(*(__nv_bfloat162*)&h2.x);
            float2 b2 = __bfloat1622float2(*(__nv_bfloat162*)&h2.y);
            float2 a3 = __bfloat1622float2(*(__nv_bfloat162*)&h3.x);
            float2 b3 = __bfloat1622float2(*(__nv_bfloat162*)&h3.y);
            acc.x += a0.x * w0 + a1.x * w1 + a2.x * w2 + a3.x * w3;
            acc.y += a0.y * w0 + a1.y * w1 + a2.y * w2 + a3.y * w3;
            acc.z += b0.x * w0 + b1.x * w1 + b2.x * w2 + b3.x * w3;
            acc.w += b0.y * w0 + b1.y * w1 + b2.y * w2 + b3.y * w3;
        }
        for (; e < end; e++) {
            int2 pe = __ldg(&g_pe[e]);
            float w = __int_as_float(pe.y);
            uint2 hv = __ldg((const uint2*)(g_h + (size_t)pe.x * DHID) + lane);
            float2 f0 = __bfloat1622float2(*(__nv_bfloat162*)&hv.x);
            float2 f1 = __bfloat1622float2(*(__nv_bfloat162*)&hv.y);
            acc.x += f0.x * w; acc.y += f0.y * w;
            acc.z += f1.x * w; acc.w += f1.y * w;
        }
        ((float4*)(g_agg + (size_t)n * DHID))[lane] = acc;
        s4.x += acc.x; s4.y += acc.y; s4.z += acc.z; s4.w += acc.w;
        q4.x += acc.x * acc.x; q4.y += acc.y * acc.y;
        q4.z += acc.z * acc.z; q4.w += acc.w * acc.w;
    }

    __shared__ float st[2 * DHID];
    if (threadIdx.x < 2 * DHID) st[threadIdx.x] = 0.f;
    __syncthreads();
    int c = lane * 4;
    atomicAdd(&st[c + 0], s4.x); atomicAdd(&st[c + 1], s4.y);
    atomicAdd(&st[c + 2], s4.z); atomicAdd(&st[c + 3], s4.w);
    atomicAdd(&st[DHID + c + 0], q4.x); atomicAdd(&st[DHID + c + 1], q4.y);
    atomicAdd(&st[DHID + c + 2], q4.z); atomicAdd(&st[DHID + c + 3], q4.w);
    __syncthreads();
    if (threadIdx.x < 2 * DHID) atomicAdd(&g_stats[threadIdx.x], st[threadIdx.x]);
}

// ---------------- BN finalize ------------------------------------------------
__global__ void bn_finalize_kernel(const float* __restrict__ gamma,
                                   const float* __restrict__ beta) {
    int c = threadIdx.x;
    const float invN = 1.0f / (float)NNODES;
    float mu = g_stats[c] * invN;
    float var = g_stats[DHID + c] * invN - mu * mu;
    float sc = gamma[c] * rsqrtf(var + 1e-5f);
    g_bnsc[c] = sc;
    g_bnsh[c] = beta[c] - mu * sc;
    g_stats[c] = 0.f;
    g_stats[DHID + c] = 0.f;
}

// ---------------- final: s = sum_n w_out[n] * relu(bn(agg[n])) ---------------
__global__ void node_reduce_kernel() {
    int c = threadIdx.x;
    float sc = g_bnsc[c], sh = g_bnsh[c];
    float s = 0.f;
    for (int n = blockIdx.x; n < NNODES; n += gridDim.x) {
        float v = g_agg[(size_t)n * DHID + c];
        v = fmaxf(0.f, v * sc + sh);
        s += v * g_wout[n];
    }
    atomicAdd(&g_s[c], s);
}

__global__ void final_kernel(const float* __restrict__ W2,
                             const float* __restrict__ b2,
                             float* __restrict__ out) {
    int j = threadIdx.x;
    if (j < DOUT) {
        float acc = 0.f;
        for (int k = 0; k < DHID; k++) acc += g_s[k] * W2[k * DOUT + j];
        out[j] = acc + (float)NNODES * b2[j];
    }
}

// ----------------------------------------------------------------------------
#define GEMM_SMEM (2 * 128 * ST * 2)   // 69632 bytes

extern "C" void kernel_launch(void* const* d_in, const int* in_sizes, int n_in,
                              void* d_out, int out_size) {
    const float* nf  = (const float*)d_in[0];
    const int*   ei  = (const int*)d_in[1];
    const float* ew  = (const float*)d_in[2];
    const float* W0  = (const float*)d_in[3];
    // b0 (d_in[4]) and b1 (d_in[6]) cancel exactly through BatchNorm
    const float* W1  = (const float*)d_in[5];
    const float* W2  = (const float*)d_in[7];
    const float* b2  = (const float*)d_in[8];
    const float* g0  = (const float*)d_in[9];
    const float* be0 = (const float*)d_in[10];
    const float* g1  = (const float*)d_in[11];
    const float* be1 = (const float*)d_in[12];
    const int* src = ei;
    const int* dst = ei + NEDGES;
    float* out = (float*)d_out;

    static int smem_set = 0;
    if (!smem_set) {
        cudaFuncSetAttribute(gemm_hmma_kernel,
                             cudaFuncAttributeMaxDynamicSharedMemorySize,
                             GEMM_SMEM);
        smem_set = 1;
    }

    // CSR build (by dst) + w_out histogram, reused by both conv layers
    zero_init_kernel<<<512, 256>>>();
    hist_kernel<<<1024, 256>>>(src, dst, ew);
    scan_kernel<<<1, 1024>>>();
    permute_kernel<<<1024, 256>>>(src, dst, ew);

    // layer 0
    gemm_hmma_kernel<<<NTILES, 256, GEMM_SMEM>>>(nf, W0, 0);
    gather_conv_kernel<<<1024, 256>>>();
    bn_finalize_kernel<<<1, 128>>>(g0, be0);

    // layer 1 (BN0+ReLU fused into A-staging)
    gemm_hmma_kernel<<<NTILES, 256, GEMM_SMEM>>>(nullptr, W1, 1);
    gather_conv_kernel<<<1024, 256>>>();
    bn_finalize_kernel<<<1, 128>>>(g1, be1);

    // final conv collapsed twice: edge sum == w_out-weighted node sum
    node_reduce_kernel<<<2048, 128>>>();
    final_kernel<<<1, 64>>>(W2, b2, out);
}